// round 1
// baseline (speedup 1.0000x reference)
#include <cuda_runtime.h>

// Problem constants (fixed by setup_inputs): B=256, D=256, F=512
#define Bc 256
#define Dc 256
#define Fc 512

__device__ float g_M[Fc * Fc];    // mean_b z_i z_j
__device__ float g_XZ[Dc * Fc];   // mean_b x_d z_i
__device__ float g_G[Fc * Fc];    // (p^2 - mu_t) * M
__device__ float g_zbar[Fc];      // column means of z
__device__ float g_r[Fc];         // (1/F) row sums of G
__device__ float g_diag[Fc];      // p - diag(mu_t)

// ---------------------------------------------------------------------------
// TN gemm: C[m,n] = scale * sum_k A[k*lda + m] * B[k*ldb + n]
// 32x32 tile, BK=32, 16x16 threads, 2x2 per thread.
// ---------------------------------------------------------------------------
__global__ void __launch_bounds__(256) gemm_tn_k(
    const float* __restrict__ A, const float* __restrict__ B,
    float* __restrict__ C, int K, int N, int lda, int ldb, float scale)
{
    __shared__ float As[32][32];
    __shared__ float Bs[32][32];
    const int tx = threadIdx.x, ty = threadIdx.y;
    const int tid = ty * 16 + tx;
    const int m0 = blockIdx.y * 32, n0 = blockIdx.x * 32;
    const int lr = tid >> 3;          // 0..31 (k within tile)
    const int lc = (tid & 7) << 2;    // 0,4,...,28

    float acc00 = 0.f, acc01 = 0.f, acc10 = 0.f, acc11 = 0.f;

    for (int k0 = 0; k0 < K; k0 += 32) {
        float4 a = *(const float4*)&A[(k0 + lr) * lda + m0 + lc];
        float4 b = *(const float4*)&B[(k0 + lr) * ldb + n0 + lc];
        *(float4*)&As[lr][lc] = a;
        *(float4*)&Bs[lr][lc] = b;
        __syncthreads();
#pragma unroll
        for (int k = 0; k < 32; k++) {
            float2 av = *(const float2*)&As[k][ty * 2];
            float2 bv = *(const float2*)&Bs[k][tx * 2];
            acc00 += av.x * bv.x; acc01 += av.x * bv.y;
            acc10 += av.y * bv.x; acc11 += av.y * bv.y;
        }
        __syncthreads();
    }
    const int m = m0 + ty * 2, n = n0 + tx * 2;
    C[m * N + n]           = acc00 * scale;
    C[m * N + n + 1]       = acc01 * scale;
    C[(m + 1) * N + n]     = acc10 * scale;
    C[(m + 1) * N + n + 1] = acc11 * scale;
}

// ---------------------------------------------------------------------------
// Column means of z: zbar[f] = mean_b z[b,f]
// ---------------------------------------------------------------------------
__global__ void zbar_k(const float* __restrict__ Z)
{
    const int f = blockIdx.x * blockDim.x + threadIdx.x;
    float s = 0.f;
#pragma unroll 4
    for (int b = 0; b < Bc; b++) s += Z[b * Fc + f];
    g_zbar[f] = s * (1.0f / Bc);
}

// ---------------------------------------------------------------------------
// Per-row elementwise pass over (F,F):
//   mu_t  = 0.95*mu + 0.05*M
//   dmu   = 0.05*(M - mu)            -> output
//   G     = (p^2 - mu_t) * M         -> scratch
//   r[i]  = (1/F) sum_j G[i,j]       -> scratch
//   diag  = p - mu_t[i,i]            -> dbias_f, dbias_p outputs + scratch
// ---------------------------------------------------------------------------
__global__ void __launch_bounds__(256) prep_k(
    const float* __restrict__ mu,
    float* __restrict__ dmu_out,
    float* __restrict__ dbf_out,
    float* __restrict__ dbp_out)
{
    const int i = blockIdx.x;
    const int tid = threadIdx.x;
    const float P = 0.05f;
    float lsum = 0.f;
#pragma unroll
    for (int j = tid; j < Fc; j += 256) {
        const int idx = i * Fc + j;
        float m   = g_M[idx];
        float muv = mu[idx];
        float mut = 0.95f * muv + 0.05f * m;
        dmu_out[idx] = 0.05f * (m - muv);
        float G = (P * P - mut) * m;
        g_G[idx] = G;
        lsum += G;
        if (j == i) {
            float db = P - mut;
            g_diag[i] = db;
            dbf_out[i] = db;
            dbp_out[i] = db;
        }
    }
    __shared__ float red[256];
    red[tid] = lsum;
    __syncthreads();
#pragma unroll
    for (int s = 128; s > 0; s >>= 1) {
        if (tid < s) red[tid] += red[tid + s];
        __syncthreads();
    }
    if (tid == 0) g_r[i] = red[0] * (1.0f / Fc);
}

// ---------------------------------------------------------------------------
// NT gemm with fused dkernel_f epilogue:
//   cross[d,i] = sum_j WF[d,j] * G[i,j]
//   dkf[d,i] = diag[i]*(XZ[d,i] - WF[d,i]*zbar[i]) + WF[d,i]*r[i] - cross/F
// ---------------------------------------------------------------------------
__global__ void __launch_bounds__(256) dwf_gemm_nt_k(
    const float* __restrict__ WF,   // D x F
    float* __restrict__ out)        // D x F
{
    __shared__ float As[32][33];    // As[k][d], transposed on load, +1 pad
    __shared__ float Bs[32][33];    // Bs[k][i]
    const int tx = threadIdx.x, ty = threadIdx.y;
    const int tid = ty * 16 + tx;
    const int d0 = blockIdx.y * 32, i0 = blockIdx.x * 32;
    const int lr = tid >> 3;          // 0..31 (m within tile)
    const int lc = (tid & 7) << 2;    // 0..28 (k within tile)

    float acc00 = 0.f, acc01 = 0.f, acc10 = 0.f, acc11 = 0.f;

    for (int k0 = 0; k0 < Fc; k0 += 32) {
        float4 a = *(const float4*)&WF[(d0 + lr) * Fc + k0 + lc];
        float4 b = *(const float4*)&g_G[(i0 + lr) * Fc + k0 + lc];
        As[lc + 0][lr] = a.x; As[lc + 1][lr] = a.y;
        As[lc + 2][lr] = a.z; As[lc + 3][lr] = a.w;
        Bs[lc + 0][lr] = b.x; Bs[lc + 1][lr] = b.y;
        Bs[lc + 2][lr] = b.z; Bs[lc + 3][lr] = b.w;
        __syncthreads();
#pragma unroll
        for (int k = 0; k < 32; k++) {
            float a0 = As[k][ty * 2], a1 = As[k][ty * 2 + 1];
            float b0 = Bs[k][tx * 2], b1 = Bs[k][tx * 2 + 1];
            acc00 += a0 * b0; acc01 += a0 * b1;
            acc10 += a1 * b0; acc11 += a1 * b1;
        }
        __syncthreads();
    }

    const float invF = 1.0f / Fc;
    float accs[2][2] = {{acc00, acc01}, {acc10, acc11}};
    const int d = d0 + ty * 2, i = i0 + tx * 2;
#pragma unroll
    for (int dd = 0; dd < 2; dd++) {
#pragma unroll
        for (int ii = 0; ii < 2; ii++) {
            const int D_ = d + dd, I_ = i + ii;
            float wf = WF[D_ * Fc + I_];
            float val = g_diag[I_] * (g_XZ[D_ * Fc + I_] - wf * g_zbar[I_])
                      + wf * g_r[I_]
                      - accs[dd][ii] * invF;
            out[D_ * Fc + I_] = val;
        }
    }
}

extern "C" void kernel_launch(void* const* d_in, const int* in_sizes, int n_in,
                              void* d_out, int out_size)
{
    const float* z  = (const float*)d_in[0];   // (B,F)
    const float* x  = (const float*)d_in[1];   // (B,D)
    const float* u  = (const float*)d_in[2];   // (B,F)
    const float* td = (const float*)d_in[3];   // (B,F)
    const float* mu = (const float*)d_in[4];   // (F,F)
    const float* wf = (const float*)d_in[5];   // (D,F)
    // d_in[6] = w_p_kernel: unused by the outputs.

    float* out   = (float*)d_out;
    float* o_dmu = out;                        // F*F
    float* o_dkf = o_dmu + Fc * Fc;            // D*F
    float* o_dbf = o_dkf + Dc * Fc;            // F
    float* o_dkp = o_dbf + Fc;                 // F*F
    float* o_dbp = o_dkp + Fc * Fc;            // F

    float* dM;  cudaGetSymbolAddress((void**)&dM,  g_M);
    float* dXZ; cudaGetSymbolAddress((void**)&dXZ, g_XZ);

    const float invB = 1.0f / Bc;
    dim3 thr(16, 16);

    // M = Z^T Z / B   (512x512, K=256)
    gemm_tn_k<<<dim3(Fc / 32, Fc / 32), thr>>>(z, z, dM, Bc, Fc, Fc, Fc, invB);
    // XZ = X^T Z / B  (256x512, K=256)
    gemm_tn_k<<<dim3(Fc / 32, Dc / 32), thr>>>(x, z, dXZ, Bc, Fc, Dc, Fc, invB);
    // dkernel_p = u^T td / B  (512x512, K=256) -> straight to output
    gemm_tn_k<<<dim3(Fc / 32, Fc / 32), thr>>>(u, td, o_dkp, Bc, Fc, Fc, Fc, invB);
    // zbar
    zbar_k<<<2, 256>>>(z);
    // dmu, G, r, diag, biases
    prep_k<<<Fc, 256>>>(mu, o_dmu, o_dbf, o_dbp);
    // dkernel_f = fused epilogue on cross = WF @ G^T  (256x512, K=512)
    dwf_gemm_nt_k<<<dim3(Fc / 32, Dc / 32), thr>>>(wf, o_dkf);
}

// round 4
// speedup vs baseline: 1.9907x; 1.9907x over previous
#include <cuda_runtime.h>

// Problem constants (fixed by setup_inputs): B=256, D=256, F=512
#define Bc 256
#define Dc 256
#define Fc 512

// ---------------------------------------------------------------------------
// Scratch (static device memory; no allocs allowed). All 16B-aligned so
// float4 access is legal.
// ---------------------------------------------------------------------------
#define DEVARR __device__ __align__(16)
DEVARR float g_P0[2][Fc * Fc];   // z'z split-K halves
DEVARR float g_P1[2][Dc * Fc];   // x'z split-K halves
DEVARR float g_P2[2][Fc * Fc];   // u'td split-K halves
DEVARR float g_XZ[Dc * Fc];      // mean_b x_d z_i
DEVARR float g_G[Fc * Fc];       // (p^2 - mu_t) * M
DEVARR float g_zbar[Fc];
DEVARR float g_r[Fc];            // (1/F) row sums of G
DEVARR float g_diag[Fc];         // p - diag(mu_t)
DEVARR float g_DW[4][Dc * Fc];   // dwf split-K partials

// ---------------------------------------------------------------------------
// Mega kernel: three TN gemms (C = A^T B over K=256), 64x64 tiles, 4x4 per
// thread, BK=16, split-K=2 ... plus 16 trailing CTAs computing zbar.
//
// Tiles (160 total, x2 K-halves = 320 CTAs):
//   [0,64):    P0 = z^T z      M=512 N=512 lda=512
//   [64,96):   P1 = x^T z      M=256 N=512 lda=256
//   [96,160):  P2 = u^T td     M=512 N=512 lda=512
// CTAs [320,336): zbar
// ---------------------------------------------------------------------------
__global__ void __launch_bounds__(256) mega_k(
    const float* __restrict__ z, const float* __restrict__ x,
    const float* __restrict__ u, const float* __restrict__ td)
{
    const int bb = blockIdx.x;
    const int tid = threadIdx.x;

    if (bb < 320) {
        const int half = bb & 1;
        const int tile = bb >> 1;

        const float *A, *B;
        float* C;
        int m_t, n_t, lda;
        if (tile < 64) {
            A = z; B = z; C = g_P0[half]; lda = Fc;
            m_t = tile >> 3; n_t = tile & 7;
        } else if (tile < 96) {
            const int t2 = tile - 64;
            A = x; B = z; C = g_P1[half]; lda = Dc;
            m_t = t2 >> 3; n_t = t2 & 7;
        } else {
            const int t2 = tile - 96;
            A = u; B = td; C = g_P2[half]; lda = Fc;
            m_t = t2 >> 3; n_t = t2 & 7;
        }
        const int m0 = m_t * 64, n0 = n_t * 64;
        const int k0 = half * 128;

        __shared__ __align__(16) float As[16][64];
        __shared__ __align__(16) float Bs[16][64];

        const int lk = tid >> 4;          // 0..15 (k within block)
        const int lm = (tid & 15) << 2;   // 0,4,...,60
        const int ty = tid >> 4;          // row group
        const int tx = tid & 15;          // col group

        float acc[4][4];
#pragma unroll
        for (int a = 0; a < 4; a++)
#pragma unroll
            for (int b = 0; b < 4; b++) acc[a][b] = 0.f;

        for (int kb = 0; kb < 128; kb += 16) {
            const int kk = k0 + kb + lk;
            *(float4*)&As[lk][lm] = *(const float4*)&A[kk * lda + m0 + lm];
            *(float4*)&Bs[lk][lm] = *(const float4*)&B[kk * Fc  + n0 + lm];
            __syncthreads();
#pragma unroll
            for (int k = 0; k < 16; k++) {
                float4 a4 = *(const float4*)&As[k][ty * 4];
                float4 b4 = *(const float4*)&Bs[k][tx * 4];
                float av[4] = {a4.x, a4.y, a4.z, a4.w};
                float bv[4] = {b4.x, b4.y, b4.z, b4.w};
#pragma unroll
                for (int a = 0; a < 4; a++)
#pragma unroll
                    for (int b = 0; b < 4; b++) acc[a][b] += av[a] * bv[b];
            }
            __syncthreads();
        }
#pragma unroll
        for (int a = 0; a < 4; a++) {
            float4 o = {acc[a][0], acc[a][1], acc[a][2], acc[a][3]};
            *(float4*)&C[(m0 + ty * 4 + a) * Fc + n0 + tx * 4] = o;
        }
    } else {
        // zbar: 16 CTAs, each covers 32 consecutive f-columns.
        const int zb = bb - 320;
        const int lane = tid & 31;
        const int w = tid >> 5;           // 0..7
        const int f = zb * 32 + lane;
        float s = 0.f;
#pragma unroll 8
        for (int b = w; b < Bc; b += 8) s += z[b * Fc + f];
        __shared__ float red[8][32];
        red[w][lane] = s;
        __syncthreads();
        if (w == 0) {
            float t = 0.f;
#pragma unroll
            for (int q = 0; q < 8; q++) t += red[q][lane];
            g_zbar[f] = t * (1.0f / Bc);
        }
    }
}

// ---------------------------------------------------------------------------
// prep: combine split-K halves + elementwise derivations.
//   rows [0,512):     M row i -> dmu, G, r, diag, biases
//   rows [512,768):   XZ row d
//   rows [768,1280):  dkernel_p row
// ---------------------------------------------------------------------------
__global__ void __launch_bounds__(256) prep_k(
    const float* __restrict__ mu,
    float* __restrict__ dmu_out,
    float* __restrict__ dbf_out,
    float* __restrict__ dbp_out,
    float* __restrict__ dkp_out)
{
    const int r = blockIdx.x;
    const int tid = threadIdx.x;
    const float invB = 1.0f / Bc;
    const float P = 0.05f;

    if (r < Fc) {
        const int i = r;
        float lsum = 0.f;
#pragma unroll
        for (int j = tid; j < Fc; j += 256) {
            const int idx = i * Fc + j;
            float m = (g_P0[0][idx] + g_P0[1][idx]) * invB;
            float muv = mu[idx];
            float mut = 0.95f * muv + 0.05f * m;
            dmu_out[idx] = 0.05f * (m - muv);
            float G = (P * P - mut) * m;
            g_G[idx] = G;
            lsum += G;
            if (j == i) {
                float db = P - mut;
                g_diag[i] = db;
                dbf_out[i] = db;
                dbp_out[i] = db;
            }
        }
        __shared__ float red[256];
        red[tid] = lsum;
        __syncthreads();
#pragma unroll
        for (int s = 128; s > 0; s >>= 1) {
            if (tid < s) red[tid] += red[tid + s];
            __syncthreads();
        }
        if (tid == 0) g_r[i] = red[0] * (1.0f / Fc);
    } else if (r < Fc + Dc) {
        const int d = r - Fc;
#pragma unroll
        for (int j = tid; j < Fc; j += 256) {
            const int idx = d * Fc + j;
            g_XZ[idx] = (g_P1[0][idx] + g_P1[1][idx]) * invB;
        }
    } else {
        const int i = r - Fc - Dc;
#pragma unroll
        for (int j = tid; j < Fc; j += 256) {
            const int idx = i * Fc + j;
            dkp_out[idx] = (g_P2[0][idx] + g_P2[1][idx]) * invB;
        }
    }
}

// ---------------------------------------------------------------------------
// dwf: cross_partial[sk][d,i] = sum_{j in K-split sk} WF[d,j] * G[i,j]
// NT gemm, 64x64 tiles, 4x4/thread, BK=16, split-K=4 -> 128 CTAs.
// Smem tiles stored [k][m] via scatter-STS. Row stride 68 floats = 272 bytes
// (multiple of 16 -> LDS.128 on every row is aligned).
// ---------------------------------------------------------------------------
__global__ void __launch_bounds__(256) dwf_k(const float* __restrict__ WF)
{
    const int bb = blockIdx.x;
    const int sk = bb >> 5;            // 0..3
    const int tile = bb & 31;
    const int d0 = (tile >> 3) * 64;   // 0..192
    const int i0 = (tile & 7) * 64;    // 0..448
    const int j0 = sk * 128;

    __shared__ __align__(16) float As[16][68];
    __shared__ __align__(16) float Bs[16][68];

    const int tid = threadIdx.x;
    const int lr = tid >> 2;           // 0..63 (m within tile)
    const int lc = (tid & 3) << 2;     // 0,4,8,12 (k within block)
    const int ty = tid >> 4;
    const int tx = tid & 15;

    float acc[4][4];
#pragma unroll
    for (int a = 0; a < 4; a++)
#pragma unroll
        for (int b = 0; b < 4; b++) acc[a][b] = 0.f;

    for (int kb = 0; kb < 128; kb += 16) {
        float4 a4 = *(const float4*)&WF [(d0 + lr) * Fc + j0 + kb + lc];
        float4 b4 = *(const float4*)&g_G[(i0 + lr) * Fc + j0 + kb + lc];
        As[lc + 0][lr] = a4.x; As[lc + 1][lr] = a4.y;
        As[lc + 2][lr] = a4.z; As[lc + 3][lr] = a4.w;
        Bs[lc + 0][lr] = b4.x; Bs[lc + 1][lr] = b4.y;
        Bs[lc + 2][lr] = b4.z; Bs[lc + 3][lr] = b4.w;
        __syncthreads();
#pragma unroll
        for (int k = 0; k < 16; k++) {
            float4 av4 = *(const float4*)&As[k][ty * 4];
            float4 bv4 = *(const float4*)&Bs[k][tx * 4];
            float av[4] = {av4.x, av4.y, av4.z, av4.w};
            float bv[4] = {bv4.x, bv4.y, bv4.z, bv4.w};
#pragma unroll
            for (int a = 0; a < 4; a++)
#pragma unroll
                for (int b = 0; b < 4; b++) acc[a][b] += av[a] * bv[b];
        }
        __syncthreads();
    }
#pragma unroll
    for (int a = 0; a < 4; a++) {
        float4 o = {acc[a][0], acc[a][1], acc[a][2], acc[a][3]};
        *(float4*)&g_DW[sk][(d0 + ty * 4 + a) * Fc + i0 + tx * 4] = o;
    }
}

// ---------------------------------------------------------------------------
// fin: combine dwf partials + dkernel_f epilogue.
//   dkf[d,i] = diag[i]*(XZ[d,i] - WF[d,i]*zbar[i]) + WF[d,i]*r[i] - cross/F
// ---------------------------------------------------------------------------
__global__ void __launch_bounds__(256) fin_k(
    const float* __restrict__ WF, float* __restrict__ out)
{
    const int idx = blockIdx.x * 256 + threadIdx.x;   // 0..32767 float4 units
    const int d = idx >> 7;                            // 128 float4 per row
    const int c4 = (idx & 127) << 2;
    const int off = d * Fc + c4;
    const float invF = 1.0f / Fc;

    float4 p0 = *(const float4*)&g_DW[0][off];
    float4 p1 = *(const float4*)&g_DW[1][off];
    float4 p2 = *(const float4*)&g_DW[2][off];
    float4 p3 = *(const float4*)&g_DW[3][off];
    float cr[4] = {p0.x + p1.x + p2.x + p3.x,
                   p0.y + p1.y + p2.y + p3.y,
                   p0.z + p1.z + p2.z + p3.z,
                   p0.w + p1.w + p2.w + p3.w};

    float4 wf4 = *(const float4*)&WF[off];
    float4 xz4 = *(const float4*)&g_XZ[off];
    float4 dg4 = *(const float4*)&g_diag[c4];
    float4 zb4 = *(const float4*)&g_zbar[c4];
    float4 rr4 = *(const float4*)&g_r[c4];

    float wf[4] = {wf4.x, wf4.y, wf4.z, wf4.w};
    float xz[4] = {xz4.x, xz4.y, xz4.z, xz4.w};
    float dg[4] = {dg4.x, dg4.y, dg4.z, dg4.w};
    float zb[4] = {zb4.x, zb4.y, zb4.z, zb4.w};
    float rr[4] = {rr4.x, rr4.y, rr4.z, rr4.w};

    float4 o;
    float* op = (float*)&o;
#pragma unroll
    for (int c = 0; c < 4; c++)
        op[c] = dg[c] * (xz[c] - wf[c] * zb[c]) + wf[c] * rr[c] - cr[c] * invF;
    *(float4*)&out[off] = o;
}

extern "C" void kernel_launch(void* const* d_in, const int* in_sizes, int n_in,
                              void* d_out, int out_size)
{
    const float* z  = (const float*)d_in[0];   // (B,F)
    const float* x  = (const float*)d_in[1];   // (B,D)
    const float* u  = (const float*)d_in[2];   // (B,F)
    const float* td = (const float*)d_in[3];   // (B,F)
    const float* mu = (const float*)d_in[4];   // (F,F)
    const float* wf = (const float*)d_in[5];   // (D,F)

    float* out   = (float*)d_out;
    float* o_dmu = out;                        // F*F
    float* o_dkf = o_dmu + Fc * Fc;            // D*F
    float* o_dbf = o_dkf + Dc * Fc;            // F
    float* o_dkp = o_dbf + Fc;                 // F*F
    float* o_dbp = o_dkp + Fc * Fc;            // F

    mega_k<<<336, 256>>>(z, x, u, td);
    prep_k<<<1280, 256>>>(mu, o_dmu, o_dbf, o_dbp, o_dkp);
    dwf_k<<<128, 256>>>(wf);
    fin_k<<<128, 256>>>(wf, o_dkf);
}